// round 1
// baseline (speedup 1.0000x reference)
#include <cuda_runtime.h>
#include <math.h>
#include <stdint.h>

#define NB    8
#define NPTS  4096
#define BN    32768
#define NEDGE 524288
#define C0    64
#define C1    128
#define C2    512

// ---------------- scratch (device globals: no allocation allowed) ----------------
__device__ float g_h0[BN * C0];      // 8 MB
__device__ float g_agg0[BN * C0];    // 8 MB
__device__ float g_h1[BN * C1];      // 16 MB
__device__ float g_agg1[BN * C1];    // 16 MB
__device__ float g_dinv[BN];
__device__ int   g_deg[BN];
__device__ float g_lat[NB * C2];
__device__ float g_lat2[NB * C2];
__device__ float g_base[NB * 6];

__device__ __forceinline__ float selu_f(float v) {
    const float scale = 1.0507009873554805f;
    const float alpha = 1.6732632423543772f;
    return v > 0.0f ? scale * v : scale * alpha * expm1f(v);
}

__device__ __forceinline__ void atomicMaxF(float* addr, float v) {
    if (v >= 0.0f) atomicMax((int*)addr, __float_as_int(v));
    else           atomicMin((unsigned int*)addr, __float_as_uint(v));
}

// ---------------- init: deg=1 (self loop), lat=-inf ----------------
__global__ void init_kernel() {
    int i = blockIdx.x * blockDim.x + threadIdx.x;
    if (i < BN) g_deg[i] = 1;
    if (i < NB * C2) g_lat[i] = __int_as_float(0xff800000);
}

// ---------------- local covariance (window 25) + 12->64 linear + selu ----------------
__global__ void cov_e1_kernel(const float* __restrict__ x,
                              const float* __restrict__ w_e1,
                              const float* __restrict__ b_e1) {
    __shared__ float nbr[4][25][3];
    __shared__ int   vld[4][25];
    __shared__ float mean[4][3];
    __shared__ float feat[4][12];
    int p = threadIdx.x >> 6;   // 4 points per block
    int c = threadIdx.x & 63;   // 64 output channels
    int point = blockIdx.x * 4 + p;
    int b = point >> 12;
    int n = point & 4095;
    if (c < 25) {
        int nn = n + c - 12;
        int v  = (nn >= 0 && nn < NPTS);
        int nc = min(max(nn, 0), NPTS - 1);
        const float* xp = x + ((size_t)b * NPTS + nc) * 3;
        nbr[p][c][0] = xp[0]; nbr[p][c][1] = xp[1]; nbr[p][c][2] = xp[2];
        vld[p][c] = v;
    }
    __syncthreads();
    if (c < 3) {
        float s = 0.0f, cnt = 0.0f;
        for (int w = 0; w < 25; w++) if (vld[p][w]) { s += nbr[p][w][c]; cnt += 1.0f; }
        mean[p][c] = s / cnt;
        feat[p][c] = nbr[p][12][c];   // the point itself
    }
    __syncthreads();
    if (c < 9) {
        int d = c / 3, e = c % 3;
        float md = mean[p][d], me = mean[p][e];
        float s = 0.0f;
        for (int w = 0; w < 25; w++)
            if (vld[p][w]) s += (nbr[p][w][d] - md) * (nbr[p][w][e] - me);
        feat[p][3 + c] = s * (1.0f / 23.0f);   // / (NS-1)
    }
    __syncthreads();
    float acc = b_e1[c];
    #pragma unroll
    for (int k = 0; k < 12; k++) acc = fmaf(feat[p][k], w_e1[k * 64 + c], acc);
    g_h0[(size_t)point * 64 + c] = selu_f(acc);
}

// ---------------- degree + dinv ----------------
__global__ void deg_kernel(const int* __restrict__ dst) {
    int e = blockIdx.x * blockDim.x + threadIdx.x;
    if (e < NEDGE) atomicAdd(&g_deg[dst[e]], 1);
}
__global__ void dinv_kernel() {
    int i = blockIdx.x * blockDim.x + threadIdx.x;
    if (i < BN) g_dinv[i] = rsqrtf((float)g_deg[i]);
}

// ---------------- GCN aggregation: agg = S @ h (S includes self loops) ----------------
template<int W>
__global__ void selfloop_kernel(const float* __restrict__ h, float* __restrict__ agg) {
    int idx = blockIdx.x * blockDim.x + threadIdx.x;
    const int G = W / 4;
    int i = idx / G, g = idx % G;
    if (i >= BN) return;
    float c = g_dinv[i]; c = c * c;
    float4 v = *reinterpret_cast<const float4*>(h + (size_t)i * W + g * 4);
    float4 o = make_float4(c * v.x, c * v.y, c * v.z, c * v.w);
    *reinterpret_cast<float4*>(agg + (size_t)i * W + g * 4) = o;
}

template<int W>
__global__ void edge_kernel(const int* __restrict__ src, const int* __restrict__ dst,
                            const float* __restrict__ h, float* __restrict__ agg) {
    int idx = blockIdx.x * blockDim.x + threadIdx.x;
    const int G = W / 4;
    int e = idx / G, g = idx % G;
    if (e >= NEDGE) return;
    int s = src[e], d = dst[e];
    float c = g_dinv[s] * g_dinv[d];
    float4 v = *reinterpret_cast<const float4*>(h + (size_t)s * W + g * 4);
    float* p = agg + (size_t)d * W + g * 4;
    atomicAdd(p + 0, c * v.x);
    atomicAdd(p + 1, c * v.y);
    atomicAdd(p + 2, c * v.z);
    atomicAdd(p + 3, c * v.w);
}

// ---------------- tiled fp32 GEMM: C = selu(A @ W + bias); optionally fuse max-pool ----------------
// TM=TN=64, TK=16, 256 threads, 4x4 micro-tile per thread.
template<bool DO_MAX>
__global__ void gemm_selu_kernel(const float* __restrict__ A, const float* __restrict__ Wt,
                                 const float* __restrict__ bias, float* __restrict__ C,
                                 float* __restrict__ lat, int M, int N, int K) {
    __shared__ float Ast[16][64];   // transposed A tile
    __shared__ float Ws[16][64];
    __shared__ float red[16][64];
    int tid = threadIdx.x;
    int tx = tid & 15, ty = tid >> 4;
    int row0 = blockIdx.y * 64, col0 = blockIdx.x * 64;
    float acc[4][4] = {};
    for (int k0 = 0; k0 < K; k0 += 16) {
        {
            int r  = tid >> 2;
            int kk = (tid & 3) << 2;
            float4 av = *reinterpret_cast<const float4*>(A + (size_t)(row0 + r) * K + k0 + kk);
            Ast[kk + 0][r] = av.x; Ast[kk + 1][r] = av.y;
            Ast[kk + 2][r] = av.z; Ast[kk + 3][r] = av.w;
            int wk = tid >> 4;
            int wc = (tid & 15) << 2;
            *reinterpret_cast<float4*>(&Ws[wk][wc]) =
                *reinterpret_cast<const float4*>(Wt + (size_t)(k0 + wk) * N + col0 + wc);
        }
        __syncthreads();
        #pragma unroll
        for (int k = 0; k < 16; k++) {
            float4 a = *reinterpret_cast<const float4*>(&Ast[k][ty << 2]);
            float4 w = *reinterpret_cast<const float4*>(&Ws[k][tx << 2]);
            float av[4] = {a.x, a.y, a.z, a.w};
            float wv[4] = {w.x, w.y, w.z, w.w};
            #pragma unroll
            for (int i = 0; i < 4; i++)
                #pragma unroll
                for (int j = 0; j < 4; j++)
                    acc[i][j] = fmaf(av[i], wv[j], acc[i][j]);
        }
        __syncthreads();
    }
    if (!DO_MAX) {
        #pragma unroll
        for (int i = 0; i < 4; i++) {
            int r = row0 + (ty << 2) + i;
            #pragma unroll
            for (int j = 0; j < 4; j++) {
                int c = col0 + (tx << 2) + j;
                C[(size_t)r * N + c] = selu_f(acc[i][j] + bias[c]);
            }
        }
    } else {
        // selu + max over the 64 rows of this block (all same batch: 64 | 4096)
        #pragma unroll
        for (int j = 0; j < 4; j++) {
            int c = col0 + (tx << 2) + j;
            float mv = __int_as_float(0xff800000);
            #pragma unroll
            for (int i = 0; i < 4; i++) mv = fmaxf(mv, selu_f(acc[i][j] + bias[c]));
            red[ty][(tx << 2) + j] = mv;
        }
        __syncthreads();
        #pragma unroll
        for (int s = 8; s > 0; s >>= 1) {
            if (ty < s) {
                #pragma unroll
                for (int j = 0; j < 4; j++) {
                    int cc = (tx << 2) + j;
                    red[ty][cc] = fmaxf(red[ty][cc], red[ty + s][cc]);
                }
            }
            __syncthreads();
        }
        if (ty == 0) {
            int b = row0 >> 12;
            #pragma unroll
            for (int j = 0; j < 4; j++) {
                int cc = (tx << 2) + j;
                atomicMaxF(&lat[b * C2 + col0 + cc], red[0][cc]);
            }
        }
    }
}

// ---------------- lat2 = selu(lat @ w_e2 + b_e2), 8x512x512 ----------------
__global__ void e2_kernel(const float* __restrict__ lat, const float* __restrict__ w,
                          const float* __restrict__ bias, float* __restrict__ lat2) {
    __shared__ float row[C2];
    int c = threadIdx.x;
    row[c] = lat[blockIdx.x * C2 + c];
    __syncthreads();
    float acc = bias[c];
    for (int k = 0; k < C2; k++) acc = fmaf(row[k], w[k * C2 + c], acc);
    lat2[blockIdx.x * C2 + c] = selu_f(acc);
}

// ---------------- per-batch decoder bases: lat2 . w_d{1,2}[:512,:] (48 dots) ----------------
__global__ void base_kernel(const float* __restrict__ lat2,
                            const float* __restrict__ w_d1,
                            const float* __restrict__ w_d2,
                            float* __restrict__ base) {
    int o = blockIdx.x;          // 48 = 8 batches * 6 outputs
    int b = o / 6, t = o % 6, j = t % 3;
    const float* w = (t < 3) ? w_d1 : w_d2;
    int lane = threadIdx.x;
    float s = 0.0f;
    for (int c = lane; c < C2; c += 32) s += lat2[b * C2 + c] * w[c * 3 + j];
    #pragma unroll
    for (int off = 16; off > 0; off >>= 1) s += __shfl_xor_sync(0xffffffffu, s, off);
    if (lane == 0) base[b * 6 + t] = s;
}

// ---------------- closed-form folding decoder ----------------
__global__ void final_kernel(const float* __restrict__ base,
                             const float* __restrict__ w_d1, const float* __restrict__ b_d1,
                             const float* __restrict__ w_d2, const float* __restrict__ b_d2,
                             float* __restrict__ out) {
    int idx = blockIdx.x * blockDim.x + threadIdx.x;   // 32768
    int b = idx >> 12, n = idx & 4095;
    int ix = n / 46, iy = n % 46;                      // nx=91, ny=46 grid
    float y0 = 1.0f + ix * (119.0f / 90.0f);           // linspace(1,120,91)
    float y1 = 1.0f + iy * (59.0f / 45.0f);            // linspace(1,60,46)
    float kk[3];
    #pragma unroll
    for (int j = 0; j < 3; j++)
        kk[j] = selu_f(base[b * 6 + j] + y0 * w_d1[512 * 3 + j] + y1 * w_d1[513 * 3 + j] + b_d1[j]);
    #pragma unroll
    for (int j = 0; j < 3; j++) {
        float v = base[b * 6 + 3 + j]
                + kk[0] * w_d2[512 * 3 + j]
                + kk[1] * w_d2[513 * 3 + j]
                + kk[2] * w_d2[514 * 3 + j]
                + b_d2[j];
        out[(size_t)idx * 3 + j] = selu_f(v);
    }
}

// ---------------- launch ----------------
extern "C" void kernel_launch(void* const* d_in, const int* in_sizes, int n_in,
                              void* d_out, int out_size) {
    const float* x    = (const float*)d_in[0];
    const int*   knn  = (const int*)  d_in[1];
    const float* w_e1 = (const float*)d_in[2];
    const float* b_e1 = (const float*)d_in[3];
    const float* w_g1 = (const float*)d_in[4];
    const float* b_g1 = (const float*)d_in[5];
    const float* w_g2 = (const float*)d_in[6];
    const float* b_g2 = (const float*)d_in[7];
    const float* w_e2 = (const float*)d_in[8];
    const float* b_e2 = (const float*)d_in[9];
    const float* w_d1 = (const float*)d_in[10];
    const float* b_d1 = (const float*)d_in[11];
    const float* w_d2 = (const float*)d_in[12];
    const float* b_d2 = (const float*)d_in[13];
    float* out = (float*)d_out;
    const int* src = knn;
    const int* dst = knn + NEDGE;

    float *p_h0, *p_agg0, *p_h1, *p_agg1, *p_lat, *p_lat2, *p_base;
    cudaGetSymbolAddress((void**)&p_h0,   g_h0);
    cudaGetSymbolAddress((void**)&p_agg0, g_agg0);
    cudaGetSymbolAddress((void**)&p_h1,   g_h1);
    cudaGetSymbolAddress((void**)&p_agg1, g_agg1);
    cudaGetSymbolAddress((void**)&p_lat,  g_lat);
    cudaGetSymbolAddress((void**)&p_lat2, g_lat2);
    cudaGetSymbolAddress((void**)&p_base, g_base);

    init_kernel<<<BN / 256, 256>>>();
    cov_e1_kernel<<<BN / 4, 256>>>(x, w_e1, b_e1);
    deg_kernel<<<NEDGE / 256, 256>>>(dst);
    dinv_kernel<<<BN / 256, 256>>>();

    // GCN layer 1: aggregate at width 64, then 64->128 gemm+selu
    selfloop_kernel<C0><<<(BN * (C0 / 4)) / 256, 256>>>(p_h0, p_agg0);
    edge_kernel<C0><<<(NEDGE * (C0 / 4)) / 256, 256>>>(src, dst, p_h0, p_agg0);
    gemm_selu_kernel<false><<<dim3(C1 / 64, BN / 64), 256>>>(p_agg0, w_g1, b_g1, p_h1, nullptr, BN, C1, C0);

    // GCN layer 2: aggregate at width 128, then 128->512 gemm+selu fused with max-pool
    selfloop_kernel<C1><<<(BN * (C1 / 4)) / 256, 256>>>(p_h1, p_agg1);
    edge_kernel<C1><<<(NEDGE * (C1 / 4)) / 256, 256>>>(src, dst, p_h1, p_agg1);
    gemm_selu_kernel<true><<<dim3(C2 / 64, BN / 64), 256>>>(p_agg1, w_g2, b_g2, nullptr, p_lat, BN, C2, C1);

    e2_kernel<<<NB, C2>>>(p_lat, w_e2, b_e2, p_lat2);
    base_kernel<<<NB * 6, 32>>>(p_lat2, w_d1, w_d2, p_base);
    final_kernel<<<BN / 256, 256>>>(p_base, w_d1, b_d1, w_d2, b_d2, out);
}

// round 2
// speedup vs baseline: 1.4211x; 1.4211x over previous
#include <cuda_runtime.h>
#include <math.h>
#include <stdint.h>

#define NB    8
#define NPTS  4096
#define BN    32768
#define NEDGE 524288
#define C0    64
#define C1    128
#define C2    512

// ---------------- scratch (device globals) ----------------
__device__ float g_h0[BN * C0];      // hs0 = dinv * h0
__device__ float g_agg0[BN * C0];    // starts as hs0 (self loop), edges add
__device__ float g_h1[BN * C1];      // hs1 = dinv * h1
__device__ float g_agg1[BN * C1];
__device__ float g_dinv[BN];
__device__ int   g_deg[BN];
__device__ float g_lat[NB * C2];
__device__ float g_lat2[NB * C2];
__device__ float g_base[NB * 6];

__device__ __forceinline__ float selu_f(float v) {
    const float scale = 1.0507009873554805f;
    const float alpha = 1.6732632423543772f;
    return v > 0.0f ? scale * v : scale * alpha * expm1f(v);
}

__device__ __forceinline__ void atomicMaxF(float* addr, float v) {
    if (v >= 0.0f) atomicMax((int*)addr, __float_as_int(v));
    else           atomicMin((unsigned int*)addr, __float_as_uint(v));
}

__device__ __forceinline__ void red_add_v4(float* p, float4 v) {
    asm volatile("red.global.add.v4.f32 [%0], {%1,%2,%3,%4};"
                 :: "l"(p), "f"(v.x), "f"(v.y), "f"(v.z), "f"(v.w) : "memory");
}

// ---------------- init: deg=1 (self loop), lat=-inf ----------------
__global__ void init_kernel() {
    int i = blockIdx.x * blockDim.x + threadIdx.x;
    if (i < BN) g_deg[i] = 1;
    if (i < NB * C2) g_lat[i] = __int_as_float(0xff800000);
}

// ---------------- degree + dinv ----------------
__global__ void deg_kernel(const int* __restrict__ dst) {
    int e = blockIdx.x * blockDim.x + threadIdx.x;
    if (e < NEDGE) atomicAdd(&g_deg[dst[e]], 1);
}
__global__ void dinv_kernel() {
    int i = blockIdx.x * blockDim.x + threadIdx.x;
    if (i < BN) g_dinv[i] = rsqrtf((float)g_deg[i]);
}

// ---------------- local covariance + 12->64 linear + selu; writes hs0 to h0 AND agg0 ----------------
__global__ void cov_e1_kernel(const float* __restrict__ x,
                              const float* __restrict__ w_e1,
                              const float* __restrict__ b_e1) {
    __shared__ float nbr[4][25][3];
    __shared__ int   vld[4][25];
    __shared__ float mean[4][3];
    __shared__ float feat[4][12];
    int p = threadIdx.x >> 6;
    int c = threadIdx.x & 63;
    int point = blockIdx.x * 4 + p;
    int b = point >> 12;
    int n = point & 4095;
    if (c < 25) {
        int nn = n + c - 12;
        int v  = (nn >= 0 && nn < NPTS);
        int nc = min(max(nn, 0), NPTS - 1);
        const float* xp = x + ((size_t)b * NPTS + nc) * 3;
        nbr[p][c][0] = xp[0]; nbr[p][c][1] = xp[1]; nbr[p][c][2] = xp[2];
        vld[p][c] = v;
    }
    __syncthreads();
    if (c < 3) {
        float s = 0.0f, cnt = 0.0f;
        for (int w = 0; w < 25; w++) if (vld[p][w]) { s += nbr[p][w][c]; cnt += 1.0f; }
        mean[p][c] = s / cnt;
        feat[p][c] = nbr[p][12][c];
    }
    __syncthreads();
    if (c < 9) {
        int d = c / 3, e = c % 3;
        float md = mean[p][d], me = mean[p][e];
        float s = 0.0f;
        for (int w = 0; w < 25; w++)
            if (vld[p][w]) s += (nbr[p][w][d] - md) * (nbr[p][w][e] - me);
        feat[p][3 + c] = s * (1.0f / 23.0f);
    }
    __syncthreads();
    float acc = b_e1[c];
    #pragma unroll
    for (int k = 0; k < 12; k++) acc = fmaf(feat[p][k], w_e1[k * 64 + c], acc);
    float hs = g_dinv[point] * selu_f(acc);
    g_h0[(size_t)point * 64 + c]   = hs;
    g_agg0[(size_t)point * 64 + c] = hs;
}

// ---------------- edge scatter: agg[d] += hs[s] (vector red) ----------------
template<int LOGG>
__global__ void edge_kernel(const int* __restrict__ src, const int* __restrict__ dst,
                            const float* __restrict__ hs, float* __restrict__ agg) {
    int idx = blockIdx.x * blockDim.x + threadIdx.x;
    int e = idx >> LOGG;
    int g = idx & ((1 << LOGG) - 1);
    if (e >= NEDGE) return;
    int s = src[e], d = dst[e];
    float4 v = *reinterpret_cast<const float4*>(hs + ((size_t)s << (LOGG + 2)) + (g << 2));
    red_add_v4(agg + ((size_t)d << (LOGG + 2)) + (g << 2), v);
}

// ---------------- GEMM: out = selu( (dinv[row]*A[row]) @ W + bias ) ----------------
// 128x128 tile, BK=16, 256 threads, 8x8 micro-tile.
// !DO_MAX: writes hs = dinv[row]*out to O1 and O2.  DO_MAX: fused selu+max-pool -> lat.
template<bool DO_MAX>
__global__ void __launch_bounds__(256)
gemm_kernel(const float* __restrict__ A, const float* __restrict__ dinv,
            const float* __restrict__ Wt, const float* __restrict__ bias,
            float* __restrict__ O1, float* __restrict__ O2,
            float* __restrict__ lat, int N, int K) {
    __shared__ float Ast[16][128];
    __shared__ float Ws[16][128];
    __shared__ float red_s[16][128];
    int tid = threadIdx.x;
    int tx = tid & 15, ty = tid >> 4;
    int row0 = blockIdx.y * 128, col0 = blockIdx.x * 128;

    int ar = tid >> 1;                 // 0..127
    int ak = (tid & 1) << 3;           // 0 or 8
    float dv = dinv[row0 + ar];
    int wk = tid >> 4;                 // 0..15
    int wc = (tid & 15) << 3;          // 0..120

    float acc[8][8] = {};
    for (int k0 = 0; k0 < K; k0 += 16) {
        float4 a0 = *reinterpret_cast<const float4*>(A + (size_t)(row0 + ar) * K + k0 + ak);
        float4 a1 = *reinterpret_cast<const float4*>(A + (size_t)(row0 + ar) * K + k0 + ak + 4);
        Ast[ak + 0][ar] = dv * a0.x; Ast[ak + 1][ar] = dv * a0.y;
        Ast[ak + 2][ar] = dv * a0.z; Ast[ak + 3][ar] = dv * a0.w;
        Ast[ak + 4][ar] = dv * a1.x; Ast[ak + 5][ar] = dv * a1.y;
        Ast[ak + 6][ar] = dv * a1.z; Ast[ak + 7][ar] = dv * a1.w;
        *reinterpret_cast<float4*>(&Ws[wk][wc]) =
            *reinterpret_cast<const float4*>(Wt + (size_t)(k0 + wk) * N + col0 + wc);
        *reinterpret_cast<float4*>(&Ws[wk][wc + 4]) =
            *reinterpret_cast<const float4*>(Wt + (size_t)(k0 + wk) * N + col0 + wc + 4);
        __syncthreads();
        #pragma unroll
        for (int k = 0; k < 16; k++) {
            float av[8], wv[8];
            *reinterpret_cast<float4*>(av)     = *reinterpret_cast<const float4*>(&Ast[k][ty << 3]);
            *reinterpret_cast<float4*>(av + 4) = *reinterpret_cast<const float4*>(&Ast[k][(ty << 3) + 4]);
            *reinterpret_cast<float4*>(wv)     = *reinterpret_cast<const float4*>(&Ws[k][tx << 3]);
            *reinterpret_cast<float4*>(wv + 4) = *reinterpret_cast<const float4*>(&Ws[k][(tx << 3) + 4]);
            #pragma unroll
            for (int i = 0; i < 8; i++)
                #pragma unroll
                for (int j = 0; j < 8; j++)
                    acc[i][j] = fmaf(av[i], wv[j], acc[i][j]);
        }
        __syncthreads();
    }

    float bv[8];
    #pragma unroll
    for (int j = 0; j < 8; j++) bv[j] = bias[col0 + (tx << 3) + j];

    if (!DO_MAX) {
        #pragma unroll
        for (int i = 0; i < 8; i++) {
            int r = row0 + (ty << 3) + i;
            float dv2 = dinv[r];
            float o[8];
            #pragma unroll
            for (int j = 0; j < 8; j++) o[j] = dv2 * selu_f(acc[i][j] + bv[j]);
            size_t base = (size_t)r * N + col0 + (tx << 3);
            *reinterpret_cast<float4*>(O1 + base)     = *reinterpret_cast<float4*>(o);
            *reinterpret_cast<float4*>(O1 + base + 4) = *reinterpret_cast<float4*>(o + 4);
            *reinterpret_cast<float4*>(O2 + base)     = *reinterpret_cast<float4*>(o);
            *reinterpret_cast<float4*>(O2 + base + 4) = *reinterpret_cast<float4*>(o + 4);
        }
    } else {
        #pragma unroll
        for (int j = 0; j < 8; j++) {
            float mv = __int_as_float(0xff800000);
            #pragma unroll
            for (int i = 0; i < 8; i++) mv = fmaxf(mv, selu_f(acc[i][j] + bv[j]));
            red_s[ty][(tx << 3) + j] = mv;
        }
        __syncthreads();
        #pragma unroll
        for (int s = 8; s > 0; s >>= 1) {
            if (ty < s) {
                #pragma unroll
                for (int j = 0; j < 8; j++) {
                    int cc = (tx << 3) + j;
                    red_s[ty][cc] = fmaxf(red_s[ty][cc], red_s[ty + s][cc]);
                }
            }
            __syncthreads();
        }
        if (ty == 0) {
            int b = row0 >> 12;
            #pragma unroll
            for (int j = 0; j < 8; j++) {
                int cc = (tx << 3) + j;
                atomicMaxF(&lat[b * C2 + col0 + cc], red_s[0][cc]);
            }
        }
    }
}

// ---------------- lat2 = selu(lat @ w_e2 + b_e2) ----------------
__global__ void e2_kernel(const float* __restrict__ lat, const float* __restrict__ w,
                          const float* __restrict__ bias, float* __restrict__ lat2) {
    __shared__ float row[C2];
    int c = threadIdx.x;
    row[c] = lat[blockIdx.x * C2 + c];
    __syncthreads();
    float acc = bias[c];
    for (int k = 0; k < C2; k++) acc = fmaf(row[k], w[k * C2 + c], acc);
    lat2[blockIdx.x * C2 + c] = selu_f(acc);
}

// ---------------- per-batch decoder bases ----------------
__global__ void base_kernel(const float* __restrict__ lat2,
                            const float* __restrict__ w_d1,
                            const float* __restrict__ w_d2,
                            float* __restrict__ base) {
    int o = blockIdx.x;
    int b = o / 6, t = o % 6, j = t % 3;
    const float* w = (t < 3) ? w_d1 : w_d2;
    int lane = threadIdx.x;
    float s = 0.0f;
    for (int c = lane; c < C2; c += 32) s += lat2[b * C2 + c] * w[c * 3 + j];
    #pragma unroll
    for (int off = 16; off > 0; off >>= 1) s += __shfl_xor_sync(0xffffffffu, s, off);
    if (lane == 0) base[b * 6 + t] = s;
}

// ---------------- closed-form folding decoder ----------------
__global__ void final_kernel(const float* __restrict__ base,
                             const float* __restrict__ w_d1, const float* __restrict__ b_d1,
                             const float* __restrict__ w_d2, const float* __restrict__ b_d2,
                             float* __restrict__ out) {
    int idx = blockIdx.x * blockDim.x + threadIdx.x;
    int b = idx >> 12, n = idx & 4095;
    int ix = n / 46, iy = n % 46;
    float y0 = 1.0f + ix * (119.0f / 90.0f);
    float y1 = 1.0f + iy * (59.0f / 45.0f);
    float kk[3];
    #pragma unroll
    for (int j = 0; j < 3; j++)
        kk[j] = selu_f(base[b * 6 + j] + y0 * w_d1[512 * 3 + j] + y1 * w_d1[513 * 3 + j] + b_d1[j]);
    #pragma unroll
    for (int j = 0; j < 3; j++) {
        float v = base[b * 6 + 3 + j]
                + kk[0] * w_d2[512 * 3 + j]
                + kk[1] * w_d2[513 * 3 + j]
                + kk[2] * w_d2[514 * 3 + j]
                + b_d2[j];
        out[(size_t)idx * 3 + j] = selu_f(v);
    }
}

// ---------------- launch ----------------
extern "C" void kernel_launch(void* const* d_in, const int* in_sizes, int n_in,
                              void* d_out, int out_size) {
    const float* x    = (const float*)d_in[0];
    const int*   knn  = (const int*)  d_in[1];
    const float* w_e1 = (const float*)d_in[2];
    const float* b_e1 = (const float*)d_in[3];
    const float* w_g1 = (const float*)d_in[4];
    const float* b_g1 = (const float*)d_in[5];
    const float* w_g2 = (const float*)d_in[6];
    const float* b_g2 = (const float*)d_in[7];
    const float* w_e2 = (const float*)d_in[8];
    const float* b_e2 = (const float*)d_in[9];
    const float* w_d1 = (const float*)d_in[10];
    const float* b_d1 = (const float*)d_in[11];
    const float* w_d2 = (const float*)d_in[12];
    const float* b_d2 = (const float*)d_in[13];
    float* out = (float*)d_out;
    const int* src = knn;
    const int* dst = knn + NEDGE;

    float *p_h0, *p_agg0, *p_h1, *p_agg1, *p_lat, *p_lat2, *p_base, *p_dinv;
    cudaGetSymbolAddress((void**)&p_h0,   g_h0);
    cudaGetSymbolAddress((void**)&p_agg0, g_agg0);
    cudaGetSymbolAddress((void**)&p_h1,   g_h1);
    cudaGetSymbolAddress((void**)&p_agg1, g_agg1);
    cudaGetSymbolAddress((void**)&p_lat,  g_lat);
    cudaGetSymbolAddress((void**)&p_lat2, g_lat2);
    cudaGetSymbolAddress((void**)&p_base, g_base);
    cudaGetSymbolAddress((void**)&p_dinv, g_dinv);

    init_kernel<<<BN / 256, 256>>>();
    deg_kernel<<<NEDGE / 256, 256>>>(dst);
    dinv_kernel<<<BN / 256, 256>>>();
    cov_e1_kernel<<<BN / 4, 256>>>(x, w_e1, b_e1);

    // GCN layer 1
    edge_kernel<4><<<(NEDGE * 16) / 256, 256>>>(src, dst, p_h0, p_agg0);
    gemm_kernel<false><<<dim3(C1 / 128, BN / 128), 256>>>(p_agg0, p_dinv, w_g1, b_g1,
                                                          p_h1, p_agg1, nullptr, C1, C0);
    // GCN layer 2 + fused max-pool
    edge_kernel<5><<<(NEDGE * 32) / 256, 256>>>(src, dst, p_h1, p_agg1);
    gemm_kernel<true><<<dim3(C2 / 128, BN / 128), 256>>>(p_agg1, p_dinv, w_g2, b_g2,
                                                         nullptr, nullptr, p_lat, C2, C1);

    e2_kernel<<<NB, C2>>>(p_lat, w_e2, b_e2, p_lat2);
    base_kernel<<<NB * 6, 32>>>(p_lat2, w_d1, w_d2, p_base);
    final_kernel<<<BN / 256, 256>>>(p_base, w_d1, b_d1, w_d2, b_d2, out);
}

// round 3
// speedup vs baseline: 1.4588x; 1.0265x over previous
#include <cuda_runtime.h>
#include <math.h>
#include <stdint.h>

#define NB    8
#define NPTS  4096
#define BN    32768
#define NEDGE 524288
#define C0    64
#define C1    128
#define C2    512

// ---------------- scratch ----------------
__device__ float g_h0[BN * C0];
__device__ float g_agg0[BN * C0];
__device__ float g_h1[BN * C1];
__device__ float g_agg1[BN * C1];
__device__ float g_dinv[BN];
__device__ int   g_deg[BN];
__device__ float g_lat[NB * C2];
__device__ float g_lat2[NB * C2];
__device__ float g_base[NB * 6];

__device__ __forceinline__ float selu_f(float v) {
    const float scale = 1.0507009873554805f;
    const float alpha = 1.6732632423543772f;
    return v > 0.0f ? scale * v : scale * alpha * expm1f(v);
}

__device__ __forceinline__ void atomicMaxF(float* addr, float v) {
    if (v >= 0.0f) atomicMax((int*)addr, __float_as_int(v));
    else           atomicMin((unsigned int*)addr, __float_as_uint(v));
}

__device__ __forceinline__ void red_add_v4(float* p, float4 v) {
    asm volatile("red.global.add.v4.f32 [%0], {%1,%2,%3,%4};"
                 :: "l"(p), "f"(v.x), "f"(v.y), "f"(v.z), "f"(v.w) : "memory");
}

__device__ __forceinline__ uint32_t f2tf32(float v) {
    uint32_t r;
    asm("cvt.rna.tf32.f32 %0, %1;" : "=r"(r) : "f"(v));
    return r;
}

__device__ __forceinline__ void mma_tf32(float d[4],
                                         uint32_t a0, uint32_t a1, uint32_t a2, uint32_t a3,
                                         uint32_t b0, uint32_t b1) {
    asm volatile("mma.sync.aligned.m16n8k8.row.col.f32.tf32.tf32.f32 "
                 "{%0,%1,%2,%3},{%4,%5,%6,%7},{%8,%9},{%0,%1,%2,%3};"
                 : "+f"(d[0]), "+f"(d[1]), "+f"(d[2]), "+f"(d[3])
                 : "r"(a0), "r"(a1), "r"(a2), "r"(a3), "r"(b0), "r"(b1));
}

// ---------------- init / degree ----------------
__global__ void init_kernel() {
    int i = blockIdx.x * blockDim.x + threadIdx.x;
    if (i < BN) g_deg[i] = 1;
    if (i < NB * C2) g_lat[i] = __int_as_float(0xff800000);
}
__global__ void deg_kernel(const int* __restrict__ dst) {
    int e = blockIdx.x * blockDim.x + threadIdx.x;
    if (e < NEDGE) atomicAdd(&g_deg[dst[e]], 1);
}
__global__ void dinv_kernel() {
    int i = blockIdx.x * blockDim.x + threadIdx.x;
    if (i < BN) g_dinv[i] = rsqrtf((float)g_deg[i]);
}

// ---------------- cov + 12->64 + selu; writes hs0 to h0 AND agg0 ----------------
// 128 threads = 128 consecutive points of one batch segment.
__global__ void __launch_bounds__(128)
cov_e1_kernel(const float* __restrict__ x,
              const float* __restrict__ w_e1,
              const float* __restrict__ b_e1) {
    __shared__ float xw[152][3];
    __shared__ float ws[12 * 64];
    __shared__ float bs[64];
    __shared__ float out_s[128][68];
    int t = threadIdx.x;
    int blk = blockIdx.x;
    int b = blk >> 5;                 // 32 blocks per batch
    int n_base = (blk & 31) << 7;     // batch-local start point
    int point0 = blk << 7;

    for (int i = t; i < 152; i += 128) {
        int idx = n_base + i - 12;
        idx = min(max(idx, 0), NPTS - 1);
        const float* xp = x + (((size_t)b << 12) + idx) * 3;
        xw[i][0] = xp[0]; xw[i][1] = xp[1]; xw[i][2] = xp[2];
    }
    for (int i = t; i < 12 * 64; i += 128) ws[i] = w_e1[i];
    if (t < 64) bs[t] = b_e1[t];
    __syncthreads();

    int n = n_base + t;
    float m0 = 0.f, m1 = 0.f, m2 = 0.f, cnt = 0.f;
    #pragma unroll
    for (int w = 0; w < 25; w++) {
        int nn = n + w - 12;
        if (nn >= 0 && nn < NPTS) {
            m0 += xw[t + w][0]; m1 += xw[t + w][1]; m2 += xw[t + w][2];
            cnt += 1.0f;
        }
    }
    float ic = 1.0f / cnt;
    m0 *= ic; m1 *= ic; m2 *= ic;
    float c00=0,c01=0,c02=0,c11=0,c12=0,c22=0;
    #pragma unroll
    for (int w = 0; w < 25; w++) {
        int nn = n + w - 12;
        if (nn >= 0 && nn < NPTS) {
            float d0 = xw[t + w][0] - m0;
            float d1 = xw[t + w][1] - m1;
            float d2 = xw[t + w][2] - m2;
            c00 = fmaf(d0, d0, c00); c01 = fmaf(d0, d1, c01); c02 = fmaf(d0, d2, c02);
            c11 = fmaf(d1, d1, c11); c12 = fmaf(d1, d2, c12); c22 = fmaf(d2, d2, c22);
        }
    }
    const float s = 1.0f / 23.0f;
    float feat[12];
    feat[0] = xw[t + 12][0]; feat[1] = xw[t + 12][1]; feat[2] = xw[t + 12][2];
    feat[3] = c00 * s; feat[4]  = c01 * s; feat[5]  = c02 * s;
    feat[6] = c01 * s; feat[7]  = c11 * s; feat[8]  = c12 * s;
    feat[9] = c02 * s; feat[10] = c12 * s; feat[11] = c22 * s;

    float dv = g_dinv[point0 + t];
    #pragma unroll 4
    for (int j = 0; j < 64; j++) {
        float acc = bs[j];
        #pragma unroll
        for (int k = 0; k < 12; k++) acc = fmaf(feat[k], ws[k * 64 + j], acc);
        out_s[t][j] = dv * selu_f(acc);
    }
    __syncthreads();

    // coalesced write-out: 2048 float4, 128 threads -> 16 each
    for (int i = t; i < 2048; i += 128) {
        int row = i >> 4, q = i & 15;
        float4 v = *reinterpret_cast<const float4*>(&out_s[row][q << 2]);
        size_t gaddr = (size_t)(point0 + row) * 64 + (q << 2);
        *reinterpret_cast<float4*>(g_h0 + gaddr)   = v;
        *reinterpret_cast<float4*>(g_agg0 + gaddr) = v;
    }
}

// ---------------- edge scatter: agg[d] += hs[s] ----------------
template<int LOGG>
__global__ void edge_kernel(const int* __restrict__ src, const int* __restrict__ dst,
                            const float* __restrict__ hs, float* __restrict__ agg) {
    int idx = blockIdx.x * blockDim.x + threadIdx.x;
    int e = idx >> LOGG;
    int g = idx & ((1 << LOGG) - 1);
    if (e >= NEDGE) return;
    int s = src[e], d = dst[e];
    float4 v = *reinterpret_cast<const float4*>(hs + ((size_t)s << (LOGG + 2)) + (g << 2));
    red_add_v4(agg + ((size_t)d << (LOGG + 2)) + (g << 2), v);
}

// ---------------- 3xTF32 GEMM: out = selu( (dinv[row]*A[row]) @ W + bias ) ----------------
// Block tile 128(M) x 64(N), KTILE=16. 256 threads = 8 warps (wm 0..1, wn 0..3),
// warp tile 64x16, mma m16n8k8 (4 m-tiles x 2 n-tiles).
template<int N, int K, bool DO_MAX>
__global__ void __launch_bounds__(256, 2)
gemm_tf32_kernel(const float* __restrict__ A, const float* __restrict__ dinv,
                 const float* __restrict__ Wt, const float* __restrict__ bias,
                 float* __restrict__ O1, float* __restrict__ O2,
                 float* __restrict__ lat) {
    __shared__ float Ah[128][20];
    __shared__ float Al[128][20];
    __shared__ float Bh[16][72];
    __shared__ float Bl[16][72];

    int tid = threadIdx.x;
    int warp = tid >> 5, lane = tid & 31;
    int wm = warp >> 2, wn = warp & 3;
    int g = lane >> 2, c = lane & 3;
    int row0 = blockIdx.y * 128, col0 = blockIdx.x * 64;

    // loader indices
    int ar = tid >> 1;                  // A row 0..127
    float dv = dinv[row0 + ar];
    int bkr = tid >> 4;                 // B k-row 0..15
    int bn4 = tid & 15;                 // B float4 col

    float d[4][2][4];                   // [mt][nt][reg]
    #pragma unroll
    for (int mt = 0; mt < 4; mt++)
        #pragma unroll
        for (int nt = 0; nt < 2; nt++)
            #pragma unroll
            for (int r = 0; r < 4; r++) d[mt][nt][r] = 0.0f;

    for (int kt = 0; kt < K; kt += 16) {
        // load A tile (128x16) with dinv scaling + tf32 split
        #pragma unroll
        for (int i = 0; i < 2; i++) {
            int q = ((tid & 1) << 1) + i;
            float4 av = *reinterpret_cast<const float4*>(A + (size_t)(row0 + ar) * K + kt + (q << 2));
            float vv[4] = {dv * av.x, dv * av.y, dv * av.z, dv * av.w};
            #pragma unroll
            for (int j = 0; j < 4; j++) {
                uint32_t hb = f2tf32(vv[j]);
                float hf = __uint_as_float(hb);
                Ah[ar][(q << 2) + j] = hf;
                Al[ar][(q << 2) + j] = __uint_as_float(f2tf32(vv[j] - hf));
            }
        }
        // load B tile (16x64)
        {
            float4 bv = *reinterpret_cast<const float4*>(Wt + (size_t)(kt + bkr) * N + col0 + (bn4 << 2));
            float vv[4] = {bv.x, bv.y, bv.z, bv.w};
            #pragma unroll
            for (int j = 0; j < 4; j++) {
                uint32_t hb = f2tf32(vv[j]);
                float hf = __uint_as_float(hb);
                Bh[bkr][(bn4 << 2) + j] = hf;
                Bl[bkr][(bn4 << 2) + j] = __uint_as_float(f2tf32(vv[j] - hf));
            }
        }
        __syncthreads();

        #pragma unroll
        for (int ks = 0; ks < 2; ks++) {
            int k0 = ks << 3;
            uint32_t ahi[4][4], alo[4][4];
            #pragma unroll
            for (int mt = 0; mt < 4; mt++) {
                int rm = wm * 64 + mt * 16;
                ahi[mt][0] = __float_as_uint(Ah[rm + g][k0 + c]);
                ahi[mt][1] = __float_as_uint(Ah[rm + g + 8][k0 + c]);
                ahi[mt][2] = __float_as_uint(Ah[rm + g][k0 + c + 4]);
                ahi[mt][3] = __float_as_uint(Ah[rm + g + 8][k0 + c + 4]);
                alo[mt][0] = __float_as_uint(Al[rm + g][k0 + c]);
                alo[mt][1] = __float_as_uint(Al[rm + g + 8][k0 + c]);
                alo[mt][2] = __float_as_uint(Al[rm + g][k0 + c + 4]);
                alo[mt][3] = __float_as_uint(Al[rm + g + 8][k0 + c + 4]);
            }
            uint32_t bhi[2][2], blo[2][2];
            #pragma unroll
            for (int nt = 0; nt < 2; nt++) {
                int nb = wn * 16 + nt * 8;
                bhi[nt][0] = __float_as_uint(Bh[k0 + c][nb + g]);
                bhi[nt][1] = __float_as_uint(Bh[k0 + c + 4][nb + g]);
                blo[nt][0] = __float_as_uint(Bl[k0 + c][nb + g]);
                blo[nt][1] = __float_as_uint(Bl[k0 + c + 4][nb + g]);
            }
            #pragma unroll
            for (int mt = 0; mt < 4; mt++)
                #pragma unroll
                for (int nt = 0; nt < 2; nt++) {
                    mma_tf32(d[mt][nt], ahi[mt][0], ahi[mt][1], ahi[mt][2], ahi[mt][3],
                             bhi[nt][0], bhi[nt][1]);
                    mma_tf32(d[mt][nt], ahi[mt][0], ahi[mt][1], ahi[mt][2], ahi[mt][3],
                             blo[nt][0], blo[nt][1]);
                    mma_tf32(d[mt][nt], alo[mt][0], alo[mt][1], alo[mt][2], alo[mt][3],
                             bhi[nt][0], bhi[nt][1]);
                }
        }
        __syncthreads();
    }

    // bias for this thread's 4 columns
    float bv[2][2];
    #pragma unroll
    for (int nt = 0; nt < 2; nt++) {
        int cc = col0 + wn * 16 + nt * 8 + (c << 1);
        bv[nt][0] = bias[cc];
        bv[nt][1] = bias[cc + 1];
    }

    if (!DO_MAX) {
        #pragma unroll
        for (int mt = 0; mt < 4; mt++) {
            int rbase = row0 + wm * 64 + mt * 16;
            #pragma unroll
            for (int half = 0; half < 2; half++) {
                int r = rbase + g + half * 8;
                float dv2 = dinv[r];
                #pragma unroll
                for (int nt = 0; nt < 2; nt++) {
                    int cc = col0 + wn * 16 + nt * 8 + (c << 1);
                    float2 o;
                    o.x = dv2 * selu_f(d[mt][nt][half * 2 + 0] + bv[nt][0]);
                    o.y = dv2 * selu_f(d[mt][nt][half * 2 + 1] + bv[nt][1]);
                    size_t addr = (size_t)r * N + cc;
                    *reinterpret_cast<float2*>(O1 + addr) = o;
                    *reinterpret_cast<float2*>(O2 + addr) = o;
                }
            }
        }
    } else {
        float mv[2][2];
        #pragma unroll
        for (int nt = 0; nt < 2; nt++) { mv[nt][0] = mv[nt][1] = __int_as_float(0xff800000); }
        #pragma unroll
        for (int mt = 0; mt < 4; mt++)
            #pragma unroll
            for (int nt = 0; nt < 2; nt++) {
                mv[nt][0] = fmaxf(mv[nt][0], fmaxf(selu_f(d[mt][nt][0] + bv[nt][0]),
                                                   selu_f(d[mt][nt][2] + bv[nt][0])));
                mv[nt][1] = fmaxf(mv[nt][1], fmaxf(selu_f(d[mt][nt][1] + bv[nt][1]),
                                                   selu_f(d[mt][nt][3] + bv[nt][1])));
            }
        // reduce over row-groups (lanes differing in bits 2..4)
        #pragma unroll
        for (int off = 4; off <= 16; off <<= 1)
            #pragma unroll
            for (int nt = 0; nt < 2; nt++) {
                mv[nt][0] = fmaxf(mv[nt][0], __shfl_xor_sync(0xffffffffu, mv[nt][0], off));
                mv[nt][1] = fmaxf(mv[nt][1], __shfl_xor_sync(0xffffffffu, mv[nt][1], off));
            }
        if (lane < 4) {
            int b = row0 >> 12;
            #pragma unroll
            for (int nt = 0; nt < 2; nt++) {
                int cc = col0 + wn * 16 + nt * 8 + (lane << 1);
                atomicMaxF(&lat[b * C2 + cc], mv[nt][0]);
                atomicMaxF(&lat[b * C2 + cc + 1], mv[nt][1]);
            }
        }
    }
}

// ---------------- lat2 = selu(lat @ w_e2 + b_e2) ----------------
__global__ void e2_kernel(const float* __restrict__ lat, const float* __restrict__ w,
                          const float* __restrict__ bias, float* __restrict__ lat2) {
    __shared__ float row[C2];
    int c = threadIdx.x;
    row[c] = lat[blockIdx.x * C2 + c];
    __syncthreads();
    float acc = bias[c];
    #pragma unroll 8
    for (int k = 0; k < C2; k++) acc = fmaf(row[k], w[k * C2 + c], acc);
    lat2[blockIdx.x * C2 + c] = selu_f(acc);
}

// ---------------- per-batch decoder bases ----------------
__global__ void base_kernel(const float* __restrict__ lat2,
                            const float* __restrict__ w_d1,
                            const float* __restrict__ w_d2,
                            float* __restrict__ base) {
    int o = blockIdx.x;
    int b = o / 6, t = o % 6, j = t % 3;
    const float* w = (t < 3) ? w_d1 : w_d2;
    int lane = threadIdx.x;
    float s = 0.0f;
    for (int c = lane; c < C2; c += 32) s += lat2[b * C2 + c] * w[c * 3 + j];
    #pragma unroll
    for (int off = 16; off > 0; off >>= 1) s += __shfl_xor_sync(0xffffffffu, s, off);
    if (lane == 0) base[b * 6 + t] = s;
}

// ---------------- closed-form folding decoder ----------------
__global__ void final_kernel(const float* __restrict__ base,
                             const float* __restrict__ w_d1, const float* __restrict__ b_d1,
                             const float* __restrict__ w_d2, const float* __restrict__ b_d2,
                             float* __restrict__ out) {
    int idx = blockIdx.x * blockDim.x + threadIdx.x;
    int b = idx >> 12, n = idx & 4095;
    int ix = n / 46, iy = n % 46;
    float y0 = 1.0f + ix * (119.0f / 90.0f);
    float y1 = 1.0f + iy * (59.0f / 45.0f);
    float kk[3];
    #pragma unroll
    for (int j = 0; j < 3; j++)
        kk[j] = selu_f(base[b * 6 + j] + y0 * w_d1[512 * 3 + j] + y1 * w_d1[513 * 3 + j] + b_d1[j]);
    #pragma unroll
    for (int j = 0; j < 3; j++) {
        float v = base[b * 6 + 3 + j]
                + kk[0] * w_d2[512 * 3 + j]
                + kk[1] * w_d2[513 * 3 + j]
                + kk[2] * w_d2[514 * 3 + j]
                + b_d2[j];
        out[(size_t)idx * 3 + j] = selu_f(v);
    }
}

// ---------------- launch ----------------
extern "C" void kernel_launch(void* const* d_in, const int* in_sizes, int n_in,
                              void* d_out, int out_size) {
    const float* x    = (const float*)d_in[0];
    const int*   knn  = (const int*)  d_in[1];
    const float* w_e1 = (const float*)d_in[2];
    const float* b_e1 = (const float*)d_in[3];
    const float* w_g1 = (const float*)d_in[4];
    const float* b_g1 = (const float*)d_in[5];
    const float* w_g2 = (const float*)d_in[6];
    const float* b_g2 = (const float*)d_in[7];
    const float* w_e2 = (const float*)d_in[8];
    const float* b_e2 = (const float*)d_in[9];
    const float* w_d1 = (const float*)d_in[10];
    const float* b_d1 = (const float*)d_in[11];
    const float* w_d2 = (const float*)d_in[12];
    const float* b_d2 = (const float*)d_in[13];
    float* out = (float*)d_out;
    const int* src = knn;
    const int* dst = knn + NEDGE;

    float *p_h0, *p_agg0, *p_h1, *p_agg1, *p_lat, *p_lat2, *p_base, *p_dinv;
    cudaGetSymbolAddress((void**)&p_h0,   g_h0);
    cudaGetSymbolAddress((void**)&p_agg0, g_agg0);
    cudaGetSymbolAddress((void**)&p_h1,   g_h1);
    cudaGetSymbolAddress((void**)&p_agg1, g_agg1);
    cudaGetSymbolAddress((void**)&p_lat,  g_lat);
    cudaGetSymbolAddress((void**)&p_lat2, g_lat2);
    cudaGetSymbolAddress((void**)&p_base, g_base);
    cudaGetSymbolAddress((void**)&p_dinv, g_dinv);

    init_kernel<<<BN / 256, 256>>>();
    deg_kernel<<<NEDGE / 256, 256>>>(dst);
    dinv_kernel<<<BN / 256, 256>>>();
    cov_e1_kernel<<<BN / 128, 128>>>(x, w_e1, b_e1);

    // GCN layer 1
    edge_kernel<4><<<(NEDGE * 16) / 256, 256>>>(src, dst, p_h0, p_agg0);
    gemm_tf32_kernel<C1, C0, false><<<dim3(C1 / 64, BN / 128), 256>>>(
        p_agg0, p_dinv, w_g1, b_g1, p_h1, p_agg1, nullptr);

    // GCN layer 2 + fused max-pool
    edge_kernel<5><<<(NEDGE * 32) / 256, 256>>>(src, dst, p_h1, p_agg1);
    gemm_tf32_kernel<C2, C1, true><<<dim3(C2 / 64, BN / 128), 256>>>(
        p_agg1, p_dinv, w_g2, b_g2, nullptr, nullptr, p_lat);

    e2_kernel<<<NB, C2>>>(p_lat, w_e2, b_e2, p_lat2);
    base_kernel<<<NB * 6, 32>>>(p_lat2, w_d1, w_d2, p_base);
    final_kernel<<<BN / 256, 256>>>(p_base, w_d1, b_d1, w_d2, b_d2, out);
}